// round 10
// baseline (speedup 1.0000x reference)
#include <cuda_runtime.h>
#include <cuda_bf16.h>
#include <cstdint>
#include <math_constants.h>

#define NUM_CLASSES 50257
#define MAX_ROWS    4096
#define BLOCK_THREADS 512

// Cross-block reduction state (zero-init at load; all self-resetting per call).
__device__ float        g_acc;
__device__ unsigned int g_count;
// Per-row half-partials: slot [row*2+half]. Always written before read; ticket
// counter wraps 0->1->0 so every graph replay sees identical initial state.
__device__ float        g_pm[MAX_ROWS * 2];
__device__ float        g_ps[MAX_ROWS * 2];
__device__ unsigned int g_rowcnt[MAX_ROWS];

// Combine two online-softmax states (m1,s1) and (m2,s2).
__device__ __forceinline__ void combine(float& m, float& s, float mo, float so) {
    float mn = fmaxf(m, mo);
    s = s * __expf(m - mn) + so * __expf(mo - mn);
    m = mn;
}

// 512 threads x 4 CTAs/SM (regs pinned <=32) is the proven-optimal shape;
// splitting each row across 2 CTAs halves CTA duration (18.2us -> 9.1us) to
// shrink launch ramp/drain losses without changing steady-state behavior.
__global__ __launch_bounds__(BLOCK_THREADS, 4)
void sce_row_kernel(const float* __restrict__ inputs,
                    const int*   __restrict__ targets,
                    float*       __restrict__ out,
                    int nrows) {
    const int row  = blockIdx.x >> 1;
    const int half = blockIdx.x & 1;
    const int tid  = threadIdx.x;
    const float* __restrict__ p = inputs + (size_t)row * NUM_CLASSES;

    // Prefetch the target logit at block start (both halves do it; the
    // finishing CTA uses its own copy — never a serialized tail DRAM trip).
    __shared__ float sh_xt;
    if (tid == 0) {
        int t = __ldg(targets + row);
        sh_xt = __ldg(p + t);
    }

    float m = -CUDART_INF_F;
    float s = 0.0f;

    // Row partition: scalar head (<=3) -> float4 body -> scalar tail (<=3).
    int head = (int)((4u - ((((uintptr_t)p) >> 2) & 3u)) & 3u);
    if (head > NUM_CLASSES) head = NUM_CLASSES;
    const int nvec    = (NUM_CLASSES - head) >> 2;
    const int halfvec = nvec >> 1;

    const float4* __restrict__ pv = (const float4*)(p + head);

    if (half == 0) {
        // scalar head
        for (int i = tid; i < head; i += BLOCK_THREADS) {
            float x = __ldcs(p + i);
            float mn = fmaxf(m, x);
            s = s * __expf(m - mn) + __expf(x - mn);
            m = mn;
        }
        // vec [0, halfvec)
        #pragma unroll 4
        for (int i = tid; i < halfvec; i += BLOCK_THREADS) {
            float4 v = __ldcs(pv + i);
            float m4 = fmaxf(fmaxf(v.x, v.y), fmaxf(v.z, v.w));
            float mn = fmaxf(m, m4);
            s = s * __expf(m - mn)
              + __expf(v.x - mn) + __expf(v.y - mn)
              + __expf(v.z - mn) + __expf(v.w - mn);
            m = mn;
        }
    } else {
        // vec [halfvec, nvec)
        #pragma unroll 4
        for (int i = halfvec + tid; i < nvec; i += BLOCK_THREADS) {
            float4 v = __ldcs(pv + i);
            float m4 = fmaxf(fmaxf(v.x, v.y), fmaxf(v.z, v.w));
            float mn = fmaxf(m, m4);
            s = s * __expf(m - mn)
              + __expf(v.x - mn) + __expf(v.y - mn)
              + __expf(v.z - mn) + __expf(v.w - mn);
            m = mn;
        }
        // scalar tail
        const int tail_start = head + (nvec << 2);
        for (int i = tail_start + tid; i < NUM_CLASSES; i += BLOCK_THREADS) {
            float x = __ldcs(p + i);
            float mn = fmaxf(m, x);
            s = s * __expf(m - mn) + __expf(x - mn);
            m = mn;
        }
    }

    // --- warp reduction of (m, s) ---
    #pragma unroll
    for (int off = 16; off > 0; off >>= 1) {
        float mo = __shfl_down_sync(0xFFFFFFFFu, m, off);
        float so = __shfl_down_sync(0xFFFFFFFFu, s, off);
        combine(m, s, mo, so);
    }

    // --- cross-warp reduction in shared ---
    __shared__ float sh_m[BLOCK_THREADS / 32];
    __shared__ float sh_s[BLOCK_THREADS / 32];
    const int wid = tid >> 5;
    const int lid = tid & 31;
    if (lid == 0) { sh_m[wid] = m; sh_s[wid] = s; }
    __syncthreads();

    if (wid == 0) {
        const int nwarps = BLOCK_THREADS / 32;   // 16
        m = (lid < nwarps) ? sh_m[lid] : -CUDART_INF_F;
        s = (lid < nwarps) ? sh_s[lid] : 0.0f;
        #pragma unroll
        for (int off = 8; off > 0; off >>= 1) {
            float mo = __shfl_down_sync(0xFFFFFFFFu, m, off);
            float so = __shfl_down_sync(0xFFFFFFFFu, s, off);
            combine(m, s, mo, so);
        }
        if (lid == 0) {
            // publish this half's partial, then race for the row ticket
            const int slot = (row << 1) | half;
            g_pm[slot] = m;
            g_ps[slot] = s;
            __threadfence();
            unsigned int rt = atomicInc(&g_rowcnt[row], 1u);  // wraps 0->1->0
            if (rt == 1u) {
                // second arrival: partner's slot is visible (fence before inc)
                const int oslot = (row << 1) | (half ^ 1);
                float mo = *(volatile float*)&g_pm[oslot];
                float so = *(volatile float*)&g_ps[oslot];
                combine(m, s, mo, so);

                float logp = sh_xt - m - __logf(s);       // log p_t

                atomicAdd(&g_acc, logp);
                __threadfence();
                unsigned int ticket = atomicInc(&g_count, (unsigned int)(nrows - 1));
                if (ticket == (unsigned int)(nrows - 1)) {
                    float total = atomicAdd(&g_acc, 0.0f);   // coherent read
                    double scale = 1.0 - 0.154 + 0.154 / (double)NUM_CLASSES;
                    double mean_logp = (double)total / (double)nrows;
                    out[0] = (float)(-(mean_logp + log(scale)));
                    g_acc = 0.0f;                             // reset for next replay
                }
            }
        }
    }
}

extern "C" void kernel_launch(void* const* d_in, const int* in_sizes, int n_in,
                              void* d_out, int out_size) {
    const float* inputs  = (const float*)d_in[0];
    const int*   targets = (const int*)d_in[1];
    float*       out     = (float*)d_out;

    const int nrows = in_sizes[1];
    sce_row_kernel<<<nrows * 2, BLOCK_THREADS>>>(inputs, targets, out, nrows);
}

// round 11
// speedup vs baseline: 1.0313x; 1.0313x over previous
#include <cuda_runtime.h>
#include <cuda_bf16.h>
#include <cstdint>
#include <math_constants.h>

#define NUM_CLASSES 50257
#define BLOCK_THREADS 512

// Fused cross-block reduction state (zeroed at load; last block resets each call).
__device__ float        g_acc;
__device__ unsigned int g_count;

// Combine two online-softmax states (m1,s1) and (m2,s2).
__device__ __forceinline__ void combine(float& m, float& s, float mo, float so) {
    float mn = fmaxf(m, mo);
    s = s * __expf(m - mn) + so * __expf(mo - mn);
    m = mn;
}

// Release-scoped ticket increment: orders the preceding g_acc atomic without a
// gpu-scope fence (__threadfence emits CCTL.IVALL = full L1D invalidate on the
// SM, nuking co-resident CTAs' L1 state 4096x per run).
__device__ __forceinline__ unsigned int atomInc_release(unsigned int* addr, unsigned int wrap) {
    unsigned int old;
    asm volatile("atom.release.gpu.global.inc.u32 %0, [%1], %2;"
                 : "=r"(old) : "l"(addr), "r"(wrap) : "memory");
    return old;
}
// Acquire-scoped coherent read of the accumulator (pairs with releases above).
__device__ __forceinline__ float atomLoadAcq(float* addr) {
    float v;
    asm volatile("atom.acquire.gpu.global.add.f32 %0, [%1], 0f00000000;"
                 : "=f"(v) : "l"(addr) : "memory");
    return v;
}

// min-blocks=4 pins ptxas to <=32 regs: 4 CTAs/SM = 64 warps is the occupancy
// cliff this kernel lives on (proven across R5-R10).
__global__ __launch_bounds__(BLOCK_THREADS, 4)
void sce_row_kernel(const float* __restrict__ inputs,
                    const int*   __restrict__ targets,
                    float*       __restrict__ out,
                    int nrows) {
    const int row = blockIdx.x;
    const int tid = threadIdx.x;
    const float* __restrict__ p = inputs + (size_t)row * NUM_CLASSES;

    // Prefetch the target logit at block start: the DRAM round trip completes
    // during the ~18us stream instead of serializing at the end of the block.
    __shared__ float sh_xt;
    if (tid == 0) {
        int t = __ldg(targets + row);
        sh_xt = __ldg(p + t);
    }

    float m = -CUDART_INF_F;
    float s = 0.0f;

    // --- scalar head until 16B alignment (rows are only 4B-aligned) ---
    int head = (int)((4u - ((((uintptr_t)p) >> 2) & 3u)) & 3u);
    if (head > NUM_CLASSES) head = NUM_CLASSES;
    for (int i = tid; i < head; i += BLOCK_THREADS) {
        float x = __ldcs(p + i);
        float mn = fmaxf(m, x);
        s = s * __expf(m - mn) + __expf(x - mn);
        m = mn;
    }

    // --- vectorized streaming body (evict-first) ---
    const float4* __restrict__ pv = (const float4*)(p + head);
    const int nvec = (NUM_CLASSES - head) >> 2;
    #pragma unroll 4
    for (int i = tid; i < nvec; i += BLOCK_THREADS) {
        float4 v = __ldcs(pv + i);
        float m4 = fmaxf(fmaxf(v.x, v.y), fmaxf(v.z, v.w));
        float mn = fmaxf(m, m4);
        s = s * __expf(m - mn)
          + __expf(v.x - mn) + __expf(v.y - mn)
          + __expf(v.z - mn) + __expf(v.w - mn);
        m = mn;
    }

    // --- scalar tail ---
    const int tail_start = head + (nvec << 2);
    for (int i = tail_start + tid; i < NUM_CLASSES; i += BLOCK_THREADS) {
        float x = __ldcs(p + i);
        float mn = fmaxf(m, x);
        s = s * __expf(m - mn) + __expf(x - mn);
        m = mn;
    }

    // --- warp reduction of (m, s) ---
    #pragma unroll
    for (int off = 16; off > 0; off >>= 1) {
        float mo = __shfl_down_sync(0xFFFFFFFFu, m, off);
        float so = __shfl_down_sync(0xFFFFFFFFu, s, off);
        combine(m, s, mo, so);
    }

    // --- cross-warp reduction in shared ---
    __shared__ float sh_m[BLOCK_THREADS / 32];
    __shared__ float sh_s[BLOCK_THREADS / 32];
    const int wid = tid >> 5;
    const int lid = tid & 31;
    if (lid == 0) { sh_m[wid] = m; sh_s[wid] = s; }
    __syncthreads();

    if (wid == 0) {
        const int nwarps = BLOCK_THREADS / 32;   // 16
        m = (lid < nwarps) ? sh_m[lid] : -CUDART_INF_F;
        s = (lid < nwarps) ? sh_s[lid] : 0.0f;
        #pragma unroll
        for (int off = 8; off > 0; off >>= 1) {
            float mo = __shfl_down_sync(0xFFFFFFFFu, m, off);
            float so = __shfl_down_sync(0xFFFFFFFFu, s, off);
            combine(m, s, mo, so);
        }
        if (lid == 0) {
            float logp = sh_xt - m - __logf(s);       // log p_t

            // fused cross-block reduction (release/acquire, no L1D flush)
            atomicAdd(&g_acc, logp);
            unsigned int ticket = atomInc_release(&g_count, (unsigned int)(gridDim.x - 1));
            if (ticket == (unsigned int)(gridDim.x - 1)) {
                float total = atomLoadAcq(&g_acc);        // coherent read
                double scale = 1.0 - 0.154 + 0.154 / (double)NUM_CLASSES;
                double mean_logp = (double)total / (double)nrows;
                out[0] = (float)(-(mean_logp + log(scale)));
                g_acc = 0.0f;                             // reset for next replay
            }
        }
    }
}

extern "C" void kernel_launch(void* const* d_in, const int* in_sizes, int n_in,
                              void* d_out, int out_size) {
    const float* inputs  = (const float*)d_in[0];
    const int*   targets = (const int*)d_in[1];
    float*       out     = (float*)d_out;

    const int nrows = in_sizes[1];
    sce_row_kernel<<<nrows, BLOCK_THREADS>>>(inputs, targets, out, nrows);
}

// round 12
// speedup vs baseline: 1.0367x; 1.0052x over previous
#include <cuda_runtime.h>
#include <cuda_bf16.h>
#include <cstdint>
#include <math_constants.h>

#define NUM_CLASSES 50257
#define BLOCK_THREADS 512

// Fused cross-block reduction state (zeroed at load; last block resets each call).
__device__ float        g_acc;
__device__ unsigned int g_count;

// Streaming float4 load: evict-first (.cs) + 256B L2 prefetch granule.
// Sequential stream -> fewer, longer DRAM bursts -> better HBM channel efficiency.
__device__ __forceinline__ float4 ldcs256(const float4* a) {
    float4 v;
    asm volatile("ld.global.cs.L2::256B.v4.f32 {%0,%1,%2,%3}, [%4];"
                 : "=f"(v.x), "=f"(v.y), "=f"(v.z), "=f"(v.w) : "l"(a));
    return v;
}

// Combine two online-softmax states (m1,s1) and (m2,s2).
__device__ __forceinline__ void combine(float& m, float& s, float mo, float so) {
    float mn = fmaxf(m, mo);
    s = s * __expf(m - mn) + so * __expf(mo - mn);
    m = mn;
}

// min-blocks=4 pins ptxas to <=32 regs: 4 CTAs/SM = 64 warps is the occupancy
// cliff this kernel lives on (proven across R5-R11).
__global__ __launch_bounds__(BLOCK_THREADS, 4)
void sce_row_kernel(const float* __restrict__ inputs,
                    const int*   __restrict__ targets,
                    float*       __restrict__ out,
                    int nrows) {
    const int row = blockIdx.x;
    const int tid = threadIdx.x;
    const float* __restrict__ p = inputs + (size_t)row * NUM_CLASSES;

    // Prefetch the target logit at block start: the DRAM round trip completes
    // during the ~18us stream instead of serializing at the end of the block.
    __shared__ float sh_xt;
    if (tid == 0) {
        int t = __ldg(targets + row);
        sh_xt = __ldg(p + t);
    }

    float m = -CUDART_INF_F;
    float s = 0.0f;

    // --- scalar head until 16B alignment (rows are only 4B-aligned) ---
    int head = (int)((4u - ((((uintptr_t)p) >> 2) & 3u)) & 3u);
    if (head > NUM_CLASSES) head = NUM_CLASSES;
    for (int i = tid; i < head; i += BLOCK_THREADS) {
        float x = __ldcs(p + i);
        float mn = fmaxf(m, x);
        s = s * __expf(m - mn) + __expf(x - mn);
        m = mn;
    }

    // --- vectorized streaming body (evict-first, 256B L2 granule) ---
    const float4* __restrict__ pv = (const float4*)(p + head);
    const int nvec = (NUM_CLASSES - head) >> 2;
    #pragma unroll 4
    for (int i = tid; i < nvec; i += BLOCK_THREADS) {
        float4 v = ldcs256(pv + i);
        float m4 = fmaxf(fmaxf(v.x, v.y), fmaxf(v.z, v.w));
        float mn = fmaxf(m, m4);
        s = s * __expf(m - mn)
          + __expf(v.x - mn) + __expf(v.y - mn)
          + __expf(v.z - mn) + __expf(v.w - mn);
        m = mn;
    }

    // --- scalar tail ---
    const int tail_start = head + (nvec << 2);
    for (int i = tail_start + tid; i < NUM_CLASSES; i += BLOCK_THREADS) {
        float x = __ldcs(p + i);
        float mn = fmaxf(m, x);
        s = s * __expf(m - mn) + __expf(x - mn);
        m = mn;
    }

    // --- warp reduction of (m, s) ---
    #pragma unroll
    for (int off = 16; off > 0; off >>= 1) {
        float mo = __shfl_down_sync(0xFFFFFFFFu, m, off);
        float so = __shfl_down_sync(0xFFFFFFFFu, s, off);
        combine(m, s, mo, so);
    }

    // --- cross-warp reduction in shared ---
    __shared__ float sh_m[BLOCK_THREADS / 32];
    __shared__ float sh_s[BLOCK_THREADS / 32];
    const int wid = tid >> 5;
    const int lid = tid & 31;
    if (lid == 0) { sh_m[wid] = m; sh_s[wid] = s; }
    __syncthreads();

    if (wid == 0) {
        const int nwarps = BLOCK_THREADS / 32;   // 16
        m = (lid < nwarps) ? sh_m[lid] : -CUDART_INF_F;
        s = (lid < nwarps) ? sh_s[lid] : 0.0f;
        #pragma unroll
        for (int off = 8; off > 0; off >>= 1) {
            float mo = __shfl_down_sync(0xFFFFFFFFu, m, off);
            float so = __shfl_down_sync(0xFFFFFFFFu, s, off);
            combine(m, s, mo, so);
        }
        if (lid == 0) {
            float logp = sh_xt - m - __logf(s);       // log p_t

            // fused cross-block reduction
            atomicAdd(&g_acc, logp);
            __threadfence();
            unsigned int ticket = atomicInc(&g_count, (unsigned int)(gridDim.x - 1));
            if (ticket == (unsigned int)(gridDim.x - 1)) {
                float total = atomicAdd(&g_acc, 0.0f);   // coherent read
                double scale = 1.0 - 0.154 + 0.154 / (double)NUM_CLASSES;
                double mean_logp = (double)total / (double)nrows;
                out[0] = (float)(-(mean_logp + log(scale)));
                g_acc = 0.0f;                             // reset for next replay
            }
        }
    }
}

extern "C" void kernel_launch(void* const* d_in, const int* in_sizes, int n_in,
                              void* d_out, int out_size) {
    const float* inputs  = (const float*)d_in[0];
    const int*   targets = (const int*)d_in[1];
    float*       out     = (float*)d_out;

    const int nrows = in_sizes[1];
    sce_row_kernel<<<nrows, BLOCK_THREADS>>>(inputs, targets, out, nrows);
}